// round 6
// baseline (speedup 1.0000x reference)
#include <cuda_runtime.h>
#include <cuda_bf16.h>
#include <cstdint>

#define B_   8
#define C_   256
#define HW_  16384
#define CHW_ 4194304
#define EPS_ 1e-5f

// ---------------- device scratch (static; no allocation APIs) ----------------
__device__ __nv_bfloat16 g_Ah[B_ * C_ * C_];   // A hi, [b][o][c]
__device__ __nv_bfloat16 g_Al[B_ * C_ * C_];   // A lo, [b][o][c]
__device__ float g_Wt[2 * C_ * C_];            // W^T
__device__ float g_csum[B_ * C_];
__device__ float g_csumsq[B_ * C_];
__device__ float g_dd[B_ * C_];                // folded bias

// ---------------- helpers (sm_80-era instructions only) ----------------
__device__ __forceinline__ uint32_t smem_u32(const void* p) {
    uint32_t a;
    asm("{ .reg .u64 t; cvta.to.shared.u64 t, %1; cvt.u32.u64 %0, t; }" : "=r"(a) : "l"(p));
    return a;
}
__device__ __forceinline__ void cp16(uint32_t s, const void* g) {
    asm volatile("cp.async.cg.shared.global [%0], [%1], 16;" :: "r"(s), "l"(g) : "memory");
}
#define CP_COMMIT() asm volatile("cp.async.commit_group;" ::: "memory")
#define CP_WAIT0()  asm volatile("cp.async.wait_group 0;" ::: "memory")

__device__ __forceinline__ void ldm4(uint32_t r[4], uint32_t addr) {
    asm volatile("ldmatrix.sync.aligned.m8n8.x4.shared.b16 {%0,%1,%2,%3}, [%4];"
                 : "=r"(r[0]), "=r"(r[1]), "=r"(r[2]), "=r"(r[3]) : "r"(addr));
}
__device__ __forceinline__ void ldm4t(uint32_t r[4], uint32_t addr) {
    asm volatile("ldmatrix.sync.aligned.m8n8.x4.trans.shared.b16 {%0,%1,%2,%3}, [%4];"
                 : "=r"(r[0]), "=r"(r[1]), "=r"(r[2]), "=r"(r[3]) : "r"(addr));
}
__device__ __forceinline__ void mma_bf16(float d[4], const uint32_t a[4], const uint32_t* b) {
    asm volatile("mma.sync.aligned.m16n8k16.row.col.f32.bf16.bf16.f32 "
                 "{%0,%1,%2,%3}, {%4,%5,%6,%7}, {%8,%9}, {%0,%1,%2,%3};"
                 : "+f"(d[0]), "+f"(d[1]), "+f"(d[2]), "+f"(d[3])
                 : "r"(a[0]), "r"(a[1]), "r"(a[2]), "r"(a[3]), "r"(b[0]), "r"(b[1]));
}
__device__ __forceinline__ void split2(float a, float b, uint32_t& h, uint32_t& l) {
    __nv_bfloat162 hp = __floats2bfloat162_rn(a, b);
    h = *reinterpret_cast<uint32_t*>(&hp);
    float la = a - __bfloat162float(hp.x);
    float lb = b - __bfloat162float(hp.y);
    __nv_bfloat162 lp = __floats2bfloat162_rn(la, lb);
    l = *reinterpret_cast<uint32_t*>(&lp);
}

__inline__ __device__ float warpSum(float v) {
    #pragma unroll
    for (int o = 16; o > 0; o >>= 1) v += __shfl_down_sync(0xffffffffu, v, o);
    return v;
}

// ---- kernel 1: per-(b,c) sum / sumsq over the plane ----
__global__ __launch_bounds__(256) void stats_kernel(const float* __restrict__ x) {
    const int c = blockIdx.x, b = blockIdx.y;
    const float4* p = (const float4*)(x + ((size_t)b * C_ + c) * HW_);
    float s = 0.f, q = 0.f;
    for (int i = threadIdx.x; i < HW_ / 4; i += 256) {
        float4 v = p[i];
        s += v.x + v.y + v.z + v.w;
        q += v.x * v.x + v.y * v.y + v.z * v.z + v.w * v.w;
    }
    __shared__ float rs[8], rq[8];
    float ws = warpSum(s), wq = warpSum(q);
    int lane = threadIdx.x & 31, warp = threadIdx.x >> 5;
    if (lane == 0) { rs[warp] = ws; rq[warp] = wq; }
    __syncthreads();
    if (threadIdx.x == 0) {
        float ts = 0.f, tq = 0.f;
        #pragma unroll
        for (int w = 0; w < 8; w++) { ts += rs[w]; tq += rq[w]; }
        g_csum[b * C_ + c] = ts;
        g_csumsq[b * C_ + c] = tq;
    }
}

// ---- kernel 2: transpose W -> Wt ----
__global__ __launch_bounds__(256) void transpose_kernel(const float* __restrict__ W) {
    g_Wt[blockIdx.x * C_ + threadIdx.x] = W[threadIdx.x * (2 * C_) + blockIdx.x];
}

// ---- kernel 3: build A hi/lo (bf16) + folded bias ----
__global__ __launch_bounds__(256) void prep_kernel(const float* __restrict__ params) {
    const int b = blockIdx.x, t = threadIdx.x;
    const float cs = g_csum[b * C_ + t];
    const float cq = g_csumsq[b * C_ + t];
    __shared__ float sm_m[C_], sm_r[C_], rs[8], rq[8];
    __shared__ float sM, sR;
    float mean = cs * (1.f / HW_);
    float var  = cq * (1.f / HW_) - mean * mean;
    sm_m[t] = mean;
    sm_r[t] = rsqrtf(var + EPS_);
    float ws = warpSum(cs), wq = warpSum(cq);
    int lane = t & 31, warp = t >> 5;
    if (lane == 0) { rs[warp] = ws; rq[warp] = wq; }
    __syncthreads();
    if (t == 0) {
        float ts = 0.f, tq = 0.f;
        #pragma unroll
        for (int w = 0; w < 8; w++) { ts += rs[w]; tq += rq[w]; }
        float M = ts / (float)CHW_;
        float V = tq / (float)CHW_ - M * M;
        sM = M; sR = rsqrtf(V + EPS_);
    }
    __syncthreads();
    const float M = sM, R = sR;
    const int o = t;
    const float gamma = params[b * 2 * C_ + o];
    const float beta  = params[b * 2 * C_ + C_ + o];
    float accmd = 0.f, accw2 = 0.f;
    uint32_t* ah = (uint32_t*)g_Ah;
    uint32_t* al = (uint32_t*)g_Al;
    for (int c = 0; c < C_; c += 2) {
        float w1a = g_Wt[c * C_ + o],       w2a = g_Wt[(C_ + c) * C_ + o];
        float w1b = g_Wt[(c + 1) * C_ + o], w2b = g_Wt[(C_ + c + 1) * C_ + o];
        float ra = sm_r[c], ma = sm_m[c], rb = sm_r[c + 1], mb = sm_m[c + 1];
        accmd += w1a * ra * ma + w1b * rb * mb;
        accw2 += w2a + w2b;
        float Aa = gamma * (w1a * ra + w2a * R);
        float Ab = gamma * (w1b * rb + w2b * R);
        uint32_t hh, ll;
        split2(Aa, Ab, hh, ll);
        size_t bi = (((size_t)(b * C_ + o)) * C_ + c) >> 1;
        ah[bi] = hh;
        al[bi] = ll;
    }
    g_dd[b * C_ + o] = gamma * (-accmd - M * R * accw2) + beta;
}

// ---- kernel 4: fused convert+GEMM, single barrier per chunk ------------------
// CTA: M=128, N=256, Kchunk=32. 8 warps (2m x 4n), warp tile 64x64.
#define STG_STRIDE  32768
#define A_STAGE_OFF 98304
#define A_STRIDE    20480
#define CONV_OFF    159744
#define CONV_SET    33792
#define CONV_HALF   16896
#define SMEM_BYTES  227328

__global__ __launch_bounds__(256, 1) void gemm_kernel(const float* __restrict__ x,
                                                      float* __restrict__ out) {
    extern __shared__ char dsm[];
    const uint32_t sb = smem_u32(dsm);
    const int b = blockIdx.z, m0 = blockIdx.y * 128, n0 = blockIdx.x * 256;
    const int t = threadIdx.x, wid = t >> 5, lane = t & 31;
    const int m64w = (wid & 1) * 64, n64w = (wid >> 1) * 64;

    const char* xb  = (const char*)(x + (size_t)b * CHW_ + n0);
    const char* pAh = (const char*)(g_Ah + ((size_t)(b * C_ + m0)) * C_);
    const char* pAl = (const char*)(g_Al + ((size_t)(b * C_ + m0)) * C_);

    auto load_group = [&](int kcc) {
        const int s = kcc % 3;
        const uint32_t bs = sb + s * STG_STRIDE;
        #pragma unroll
        for (int i = 0; i < 8; i++) {                       // B fp32: 32 rows x 1KB
            const int idx = t + i * 256;
            const int r = idx >> 6, c16 = idx & 63;
            cp16(bs + r * 1024 + c16 * 16,
                 xb + ((size_t)(kcc * 32 + r) * HW_) * 4 + c16 * 16);
        }
        const uint32_t as = sb + A_STAGE_OFF + s * A_STRIDE;
        #pragma unroll
        for (int i = 0; i < 4; i++) {                       // A bf16 hi/lo: 2x128x64B
            const int idx = t + i * 256;
            const int half = idx >> 9, rr = (idx >> 2) & 127, c4 = idx & 3;
            const char* g = (half ? pAl : pAh) + ((size_t)rr * C_ + kcc * 32) * 2 + c4 * 16;
            cp16(as + half * 10240 + rr * 80 + c4 * 16, g);
        }
    };

    auto convert_chunk = [&](int kcc) {
        const char* stg = dsm + (kcc % 3) * STG_STRIDE;
        char* cvh = dsm + CONV_OFF + (kcc & 1) * CONV_SET;
        char* cvl = cvh + CONV_HALF;
        const int r = t >> 3;
        #pragma unroll
        for (int j = 0; j < 4; j++) {
            const int cb = (t & 7) * 8 + 64 * j;
            float4 v0 = *(const float4*)(stg + r * 1024 + cb * 4);
            float4 v1 = *(const float4*)(stg + r * 1024 + cb * 4 + 16);
            uint4 h, l;
            split2(v0.x, v0.y, h.x, l.x);
            split2(v0.z, v0.w, h.y, l.y);
            split2(v1.x, v1.y, h.z, l.z);
            split2(v1.z, v1.w, h.w, l.w);
            *(uint4*)(cvh + r * 528 + cb * 2) = h;
            *(uint4*)(cvl + r * 528 + cb * 2) = l;
        }
    };

    float acc[4][8][4];
    #pragma unroll
    for (int i = 0; i < 4; i++)
        #pragma unroll
        for (int j = 0; j < 8; j++)
            #pragma unroll
            for (int e = 0; e < 4; e++) acc[i][j][e] = 0.f;

    load_group(0); CP_COMMIT();
    load_group(1); CP_COMMIT();
    CP_WAIT0();                       // groups 0,1 landed
    __syncthreads();
    convert_chunk(0);                 // conv[0] ready (published by loop-top sync)

    for (int kc = 0; kc < 8; kc++) {
        CP_WAIT0();                   // group kc+1 landed (committed one iter ago)
        __syncthreads();              // single barrier: publishes conv writes + frees reused bufs

        // ---- MMA phase: conv set kc&1, A stage kc%3 ----
        const uint32_t as  = sb + A_STAGE_OFF + (kc % 3) * A_STRIDE;
        const uint32_t cvb = sb + CONV_OFF + (kc & 1) * CONV_SET;
        #pragma unroll
        for (int kk = 0; kk < 2; kk++) {
            uint32_t ahf[4][4], alf[4][4], bhf[4][4], blf[4][4];
            const uint32_t aoff = as + (uint32_t)(m64w + (lane & 15)) * 80
                                + kk * 32 + ((lane >> 4) * 16);
            #pragma unroll
            for (int mt = 0; mt < 4; mt++) {
                ldm4(ahf[mt], aoff + mt * 16 * 80);
                ldm4(alf[mt], aoff + 10240 + mt * 16 * 80);
            }
            const int g = lane >> 3;
            const uint32_t krow = (uint32_t)(kk * 16 + ((g & 1) << 3) + (lane & 7));
            const uint32_t boff = cvb + krow * 528 + (uint32_t)(n64w + ((g >> 1) << 3)) * 2;
            #pragma unroll
            for (int tp = 0; tp < 4; tp++) {
                ldm4t(bhf[tp], boff + tp * 32);
                ldm4t(blf[tp], boff + CONV_HALF + tp * 32);
            }
            #pragma unroll
            for (int mt = 0; mt < 4; mt++) {
                #pragma unroll
                for (int tp = 0; tp < 4; tp++) {
                    mma_bf16(acc[mt][2 * tp],     ahf[mt], &bhf[tp][0]);
                    mma_bf16(acc[mt][2 * tp + 1], ahf[mt], &bhf[tp][2]);
                    mma_bf16(acc[mt][2 * tp],     ahf[mt], &blf[tp][0]);
                    mma_bf16(acc[mt][2 * tp + 1], ahf[mt], &blf[tp][2]);
                    mma_bf16(acc[mt][2 * tp],     alf[mt], &bhf[tp][0]);
                    mma_bf16(acc[mt][2 * tp + 1], alf[mt], &bhf[tp][2]);
                }
            }
        }

        // ---- overlapped tail: convert next chunk while tensor pipe drains ----
        if (kc < 7) convert_chunk(kc + 1);
        if (kc + 2 < 8) { load_group(kc + 2); CP_COMMIT(); }
    }

    // ---- epilogue: direct stores; 4-lane groups cover aligned 32B sectors ----
    #pragma unroll
    for (int mt = 0; mt < 4; mt++) {
        const int o = m0 + m64w + mt * 16 + (lane >> 2);
        const float dv0 = g_dd[b * C_ + o];
        const float dv8 = g_dd[b * C_ + o + 8];
        float* r0 = out + ((size_t)(b * C_ + o)) * HW_;
        float* r8 = out + ((size_t)(b * C_ + o + 8)) * HW_;
        #pragma unroll
        for (int n = 0; n < 8; n++) {
            const int hw = n0 + n64w + n * 8 + (lane & 3) * 2;
            float2 v0, v1;
            v0.x = acc[mt][n][0] + dv0; v0.y = acc[mt][n][1] + dv0;
            v1.x = acc[mt][n][2] + dv8; v1.y = acc[mt][n][3] + dv8;
            *(float2*)(r0 + hw) = v0;
            *(float2*)(r8 + hw) = v1;
        }
    }
}

extern "C" void kernel_launch(void* const* d_in, const int* in_sizes, int n_in,
                              void* d_out, int out_size) {
    const float* x      = (const float*)d_in[0];
    const float* params = (const float*)d_in[1];
    const float* W      = (const float*)d_in[2];
    float* out          = (float*)d_out;

    cudaFuncSetAttribute(gemm_kernel, cudaFuncAttributeMaxDynamicSharedMemorySize, SMEM_BYTES);

    stats_kernel<<<dim3(C_, B_), 256>>>(x);
    transpose_kernel<<<2 * C_, 256>>>(W);
    prep_kernel<<<B_, 256>>>(params);
    gemm_kernel<<<dim3(HW_ / 256, C_ / 128, B_), 256, SMEM_BYTES>>>(x, out);
}

// round 7
// speedup vs baseline: 1.2636x; 1.2636x over previous
#include <cuda_runtime.h>
#include <cuda_bf16.h>
#include <cstdint>

#define B_   8
#define C_   256
#define HW_  16384
#define CHW_ 4194304
#define EPS_ 1e-5f

// ---------------- device scratch (static; no allocation APIs) ----------------
__device__ __nv_bfloat16 g_Ah[B_ * C_ * C_];   // A hi, [b][o][c]
__device__ __nv_bfloat16 g_Al[B_ * C_ * C_];   // A lo, [b][o][c]
__device__ float g_csum[B_ * C_];
__device__ float g_csumsq[B_ * C_];
__device__ float g_dd[B_ * C_];                // folded bias

// ---------------- helpers (sm_80-era instructions only) ----------------
__device__ __forceinline__ uint32_t smem_u32(const void* p) {
    uint32_t a;
    asm("{ .reg .u64 t; cvta.to.shared.u64 t, %1; cvt.u32.u64 %0, t; }" : "=r"(a) : "l"(p));
    return a;
}
__device__ __forceinline__ void cp16(uint32_t s, const void* g) {
    asm volatile("cp.async.cg.shared.global [%0], [%1], 16;" :: "r"(s), "l"(g) : "memory");
}
#define CP_COMMIT() asm volatile("cp.async.commit_group;" ::: "memory")
#define CP_WAIT1()  asm volatile("cp.async.wait_group 1;" ::: "memory")

__device__ __forceinline__ void ldm4(uint32_t r[4], uint32_t addr) {
    asm volatile("ldmatrix.sync.aligned.m8n8.x4.shared.b16 {%0,%1,%2,%3}, [%4];"
                 : "=r"(r[0]), "=r"(r[1]), "=r"(r[2]), "=r"(r[3]) : "r"(addr));
}
__device__ __forceinline__ void ldm4t(uint32_t r[4], uint32_t addr) {
    asm volatile("ldmatrix.sync.aligned.m8n8.x4.trans.shared.b16 {%0,%1,%2,%3}, [%4];"
                 : "=r"(r[0]), "=r"(r[1]), "=r"(r[2]), "=r"(r[3]) : "r"(addr));
}
__device__ __forceinline__ void mma_bf16(float d[4], const uint32_t a[4], const uint32_t* b) {
    asm volatile("mma.sync.aligned.m16n8k16.row.col.f32.bf16.bf16.f32 "
                 "{%0,%1,%2,%3}, {%4,%5,%6,%7}, {%8,%9}, {%0,%1,%2,%3};"
                 : "+f"(d[0]), "+f"(d[1]), "+f"(d[2]), "+f"(d[3])
                 : "r"(a[0]), "r"(a[1]), "r"(a[2]), "r"(a[3]), "r"(b[0]), "r"(b[1]));
}
__device__ __forceinline__ void split2(float a, float b, uint32_t& h, uint32_t& l) {
    __nv_bfloat162 hp = __floats2bfloat162_rn(a, b);
    h = *reinterpret_cast<uint32_t*>(&hp);
    float la = a - __bfloat162float(hp.x);
    float lb = b - __bfloat162float(hp.y);
    __nv_bfloat162 lp = __floats2bfloat162_rn(la, lb);
    l = *reinterpret_cast<uint32_t*>(&lp);
}

__inline__ __device__ float warpSum(float v) {
    #pragma unroll
    for (int o = 16; o > 0; o >>= 1) v += __shfl_down_sync(0xffffffffu, v, o);
    return v;
}

// ---- kernel 1: per-(b,c) sum / sumsq over the plane ----
__global__ __launch_bounds__(256) void stats_kernel(const float* __restrict__ x) {
    const int c = blockIdx.x, b = blockIdx.y;
    const float4* p = (const float4*)(x + ((size_t)b * C_ + c) * HW_);
    float s = 0.f, q = 0.f;
    for (int i = threadIdx.x; i < HW_ / 4; i += 256) {
        float4 v = p[i];
        s += v.x + v.y + v.z + v.w;
        q += v.x * v.x + v.y * v.y + v.z * v.z + v.w * v.w;
    }
    __shared__ float rs[8], rq[8];
    float ws = warpSum(s), wq = warpSum(q);
    int lane = threadIdx.x & 31, warp = threadIdx.x >> 5;
    if (lane == 0) { rs[warp] = ws; rq[warp] = wq; }
    __syncthreads();
    if (threadIdx.x == 0) {
        float ts = 0.f, tq = 0.f;
        #pragma unroll
        for (int w = 0; w < 8; w++) { ts += rs[w]; tq += rq[w]; }
        g_csum[b * C_ + c] = ts;
        g_csumsq[b * C_ + c] = tq;
    }
}

// ---- kernel 2: build A hi/lo (bf16) + folded bias. grid (8 o-chunks, B_) ----
__global__ __launch_bounds__(256) void prep_kernel(const float* __restrict__ params,
                                                   const float* __restrict__ W) {
    const int b = blockIdx.y, o0 = blockIdx.x * 32;
    const int t = threadIdx.x;
    __shared__ float sm_m[C_], sm_r[C_], rs[8], rq[8];
    __shared__ float sM, sR;
    const float cs = g_csum[b * C_ + t];
    const float cq = g_csumsq[b * C_ + t];
    float mean = cs * (1.f / HW_);
    float var  = cq * (1.f / HW_) - mean * mean;
    sm_m[t] = mean;
    sm_r[t] = rsqrtf(var + EPS_);
    float ws = warpSum(cs), wq = warpSum(cq);
    int lane = t & 31, warp = t >> 5;
    if (lane == 0) { rs[warp] = ws; rq[warp] = wq; }
    __syncthreads();
    if (t == 0) {
        float ts = 0.f, tq = 0.f;
        #pragma unroll
        for (int w = 0; w < 8; w++) { ts += rs[w]; tq += rq[w]; }
        float M = ts / (float)CHW_;
        float V = tq / (float)CHW_ - M * M;
        sM = M; sR = rsqrtf(V + EPS_);
    }
    __syncthreads();
    const float M = sM, R = sR;
    const int o = o0 + (t >> 3), lane8 = t & 7, cb = lane8 * 32;
    const float gamma = params[b * 2 * C_ + o];
    const float beta  = params[b * 2 * C_ + C_ + o];
    float accmd = 0.f, accw2 = 0.f;
    uint32_t* ah = (uint32_t*)g_Ah;
    uint32_t* al = (uint32_t*)g_Al;
    #pragma unroll
    for (int j = 0; j < 8; j++) {
        const int c = cb + j * 4;
        float4 w1 = *(const float4*)&W[(size_t)o * 512 + c];
        float4 w2 = *(const float4*)&W[(size_t)o * 512 + 256 + c];
        float r0 = sm_r[c], m0 = sm_m[c], r1 = sm_r[c+1], m1 = sm_m[c+1];
        float r2 = sm_r[c+2], m2 = sm_m[c+2], r3 = sm_r[c+3], m3 = sm_m[c+3];
        accmd += w1.x * r0 * m0 + w1.y * r1 * m1 + w1.z * r2 * m2 + w1.w * r3 * m3;
        accw2 += w2.x + w2.y + w2.z + w2.w;
        float A0 = gamma * (w1.x * r0 + w2.x * R);
        float A1 = gamma * (w1.y * r1 + w2.y * R);
        float A2 = gamma * (w1.z * r2 + w2.z * R);
        float A3 = gamma * (w1.w * r3 + w2.w * R);
        uint32_t h0, l0, h1, l1;
        split2(A0, A1, h0, l0);
        split2(A2, A3, h1, l1);
        const size_t bi = (((size_t)(b * C_ + o)) * C_ + c) >> 1;   // even -> 8B aligned
        *(uint2*)&ah[bi] = make_uint2(h0, h1);
        *(uint2*)&al[bi] = make_uint2(l0, l1);
    }
    #pragma unroll
    for (int d = 4; d > 0; d >>= 1) {
        accmd += __shfl_down_sync(0xffffffffu, accmd, d, 8);
        accw2 += __shfl_down_sync(0xffffffffu, accw2, d, 8);
    }
    if (lane8 == 0)
        g_dd[b * C_ + o] = gamma * (-accmd - M * R * accw2) + beta;
}

// ---- kernel 3: fused convert+GEMM, 1 barrier/chunk, convert-own-data ---------
// CTA: M=128, N=256, Kchunk=32. 8 warps (2m x 4n), warp tile 64x64.
#define STG_STRIDE  32768
#define A_STAGE_OFF 98304
#define A_STRIDE    20480
#define CONV_OFF    159744
#define CONV_SET    33792
#define CONV_HALF   16896
#define SMEM_BYTES  227328

__global__ __launch_bounds__(256, 1) void gemm_kernel(const float* __restrict__ x,
                                                      float* __restrict__ out) {
    extern __shared__ char dsm[];
    const uint32_t sb = smem_u32(dsm);
    const int b = blockIdx.z, m0 = blockIdx.y * 128, n0 = blockIdx.x * 256;
    const int t = threadIdx.x, wid = t >> 5, lane = t & 31;
    const int m64w = (wid & 1) * 64, n64w = (wid >> 1) * 64;

    const char* xb  = (const char*)(x + (size_t)b * CHW_ + n0);
    const char* pAh = (const char*)(g_Ah + ((size_t)(b * C_ + m0)) * C_);
    const char* pAl = (const char*)(g_Al + ((size_t)(b * C_ + m0)) * C_);

    auto load_group = [&](int kcc) {
        const int s = kcc % 3;
        const uint32_t bs = sb + s * STG_STRIDE;
        #pragma unroll
        for (int i = 0; i < 8; i++) {                       // B fp32: thread t -> (r=t>>6+4i, c16=t&63)
            const int idx = t + i * 256;
            const int r = idx >> 6, c16 = idx & 63;
            cp16(bs + r * 1024 + c16 * 16,
                 xb + ((size_t)(kcc * 32 + r) * HW_) * 4 + c16 * 16);
        }
        const uint32_t as = sb + A_STAGE_OFF + s * A_STRIDE;
        #pragma unroll
        for (int i = 0; i < 4; i++) {                       // A bf16 hi/lo: 2x128x64B
            const int idx = t + i * 256;
            const int half = idx >> 9, rr = (idx >> 2) & 127, c4 = idx & 3;
            const char* g = (half ? pAl : pAh) + ((size_t)rr * C_ + kcc * 32) * 2 + c4 * 16;
            cp16(as + half * 10240 + rr * 80 + c4 * 16, g);
        }
    };

    // converts EXACTLY the pieces this thread cp.async'd -> WAIT1 alone is sufficient
    auto convert_chunk = [&](int kcc) {
        const char* stg = dsm + (kcc % 3) * STG_STRIDE;
        char* cvh = dsm + CONV_OFF + (kcc & 1) * CONV_SET;
        char* cvl = cvh + CONV_HALF;
        const int c16 = t & 63, rb = t >> 6;
        #pragma unroll
        for (int i = 0; i < 8; i++) {
            const int r = rb + 4 * i;
            float4 v = *(const float4*)(stg + r * 1024 + c16 * 16);
            uint32_t h0, l0, h1, l1;
            split2(v.x, v.y, h0, l0);
            split2(v.z, v.w, h1, l1);
            *(uint2*)(cvh + r * 528 + c16 * 8) = make_uint2(h0, h1);
            *(uint2*)(cvl + r * 528 + c16 * 8) = make_uint2(l0, l1);
        }
    };

    float acc[4][8][4];
    #pragma unroll
    for (int i = 0; i < 4; i++)
        #pragma unroll
        for (int j = 0; j < 8; j++)
            #pragma unroll
            for (int e = 0; e < 4; e++) acc[i][j][e] = 0.f;

    load_group(0); CP_COMMIT();
    load_group(1); CP_COMMIT();
    CP_WAIT1();                        // own group 0 complete
    convert_chunk(0);                  // own data only
    __syncthreads();                   // publish conv[0] + A(0) cross-thread

    for (int kc = 0; kc < 8; kc++) {
        if (kc + 2 < 8) load_group(kc + 2);
        CP_COMMIT();                   // empty group when kc>=6 keeps WAIT1 semantics

        // ---- MMA phase: conv set kc&1, A stage kc%3 ----
        const uint32_t as  = sb + A_STAGE_OFF + (kc % 3) * A_STRIDE;
        const uint32_t cvb = sb + CONV_OFF + (kc & 1) * CONV_SET;
        #pragma unroll
        for (int kk = 0; kk < 2; kk++) {
            uint32_t ahf[4][4], alf[4][4], bhf[4][4], blf[4][4];
            const uint32_t aoff = as + (uint32_t)(m64w + (lane & 15)) * 80
                                + kk * 32 + ((lane >> 4) * 16);
            #pragma unroll
            for (int mt = 0; mt < 4; mt++) {
                ldm4(ahf[mt], aoff + mt * 16 * 80);
                ldm4(alf[mt], aoff + 10240 + mt * 16 * 80);
            }
            const int g = lane >> 3;
            const uint32_t krow = (uint32_t)(kk * 16 + ((g & 1) << 3) + (lane & 7));
            const uint32_t boff = cvb + krow * 528 + (uint32_t)(n64w + ((g >> 1) << 3)) * 2;
            #pragma unroll
            for (int tp = 0; tp < 4; tp++) {
                ldm4t(bhf[tp], boff + tp * 32);
                ldm4t(blf[tp], boff + CONV_HALF + tp * 32);
            }
            #pragma unroll
            for (int mt = 0; mt < 4; mt++) {
                #pragma unroll
                for (int tp = 0; tp < 4; tp++) {
                    mma_bf16(acc[mt][2 * tp],     ahf[mt], &bhf[tp][0]);
                    mma_bf16(acc[mt][2 * tp + 1], ahf[mt], &bhf[tp][2]);
                    mma_bf16(acc[mt][2 * tp],     ahf[mt], &blf[tp][0]);
                    mma_bf16(acc[mt][2 * tp + 1], ahf[mt], &blf[tp][2]);
                    mma_bf16(acc[mt][2 * tp],     alf[mt], &bhf[tp][0]);
                    mma_bf16(acc[mt][2 * tp + 1], alf[mt], &bhf[tp][2]);
                }
            }
        }

        CP_WAIT1();                    // own group kc+1 complete
        if (kc < 7) convert_chunk(kc + 1);   // overlaps tensor-pipe drain
        __syncthreads();               // single barrier: publish conv, recycle bufs
    }

    // ---- epilogue: direct stores; 4-lane groups cover aligned 32B sectors ----
    #pragma unroll
    for (int mt = 0; mt < 4; mt++) {
        const int o = m0 + m64w + mt * 16 + (lane >> 2);
        const float dv0 = g_dd[b * C_ + o];
        const float dv8 = g_dd[b * C_ + o + 8];
        float* r0 = out + ((size_t)(b * C_ + o)) * HW_;
        float* r8 = out + ((size_t)(b * C_ + o + 8)) * HW_;
        #pragma unroll
        for (int n = 0; n < 8; n++) {
            const int hw = n0 + n64w + n * 8 + (lane & 3) * 2;
            float2 v0, v1;
            v0.x = acc[mt][n][0] + dv0; v0.y = acc[mt][n][1] + dv0;
            v1.x = acc[mt][n][2] + dv8; v1.y = acc[mt][n][3] + dv8;
            *(float2*)(r0 + hw) = v0;
            *(float2*)(r8 + hw) = v1;
        }
    }
}

extern "C" void kernel_launch(void* const* d_in, const int* in_sizes, int n_in,
                              void* d_out, int out_size) {
    const float* x      = (const float*)d_in[0];
    const float* params = (const float*)d_in[1];
    const float* W      = (const float*)d_in[2];
    float* out          = (float*)d_out;

    cudaFuncSetAttribute(gemm_kernel, cudaFuncAttributeMaxDynamicSharedMemorySize, SMEM_BYTES);

    stats_kernel<<<dim3(C_, B_), 256>>>(x);
    prep_kernel<<<dim3(8, B_), 256>>>(params, W);
    gemm_kernel<<<dim3(HW_ / 256, C_ / 128, B_), 256, SMEM_BYTES>>>(x, out);
}

// round 8
// speedup vs baseline: 1.3387x; 1.0594x over previous
#include <cuda_runtime.h>
#include <cuda_bf16.h>
#include <cstdint>

#define B_   8
#define C_   256
#define HW_  16384
#define CHW_ 4194304
#define EPS_ 1e-5f

// ---------------- device scratch (static; no allocation APIs) ----------------
__device__ __nv_bfloat16 g_xh[(size_t)B_ * C_ * HW_];  // x hi, [b][c][hw] (64 MiB)
__device__ __nv_bfloat16 g_xl[(size_t)B_ * C_ * HW_];  // x lo, [b][c][hw]
__device__ __nv_bfloat16 g_Ah[B_ * C_ * C_];           // A hi, [b][o][c]
__device__ __nv_bfloat16 g_Al[B_ * C_ * C_];           // A lo, [b][o][c]
__device__ float g_csum[B_ * C_];
__device__ float g_csumsq[B_ * C_];
__device__ float g_dd[B_ * C_];                        // folded bias

// ---------------- helpers (sm_80-era instructions only) ----------------
__device__ __forceinline__ uint32_t smem_u32(const void* p) {
    uint32_t a;
    asm("{ .reg .u64 t; cvta.to.shared.u64 t, %1; cvt.u32.u64 %0, t; }" : "=r"(a) : "l"(p));
    return a;
}
__device__ __forceinline__ void cp16(uint32_t s, const void* g) {
    asm volatile("cp.async.cg.shared.global [%0], [%1], 16;" :: "r"(s), "l"(g) : "memory");
}
#define CP_COMMIT() asm volatile("cp.async.commit_group;" ::: "memory")
#define CP_WAIT1()  asm volatile("cp.async.wait_group 1;" ::: "memory")

__device__ __forceinline__ void ldm4(uint32_t r[4], uint32_t addr) {
    asm volatile("ldmatrix.sync.aligned.m8n8.x4.shared.b16 {%0,%1,%2,%3}, [%4];"
                 : "=r"(r[0]), "=r"(r[1]), "=r"(r[2]), "=r"(r[3]) : "r"(addr));
}
__device__ __forceinline__ void ldm4t(uint32_t r[4], uint32_t addr) {
    asm volatile("ldmatrix.sync.aligned.m8n8.x4.trans.shared.b16 {%0,%1,%2,%3}, [%4];"
                 : "=r"(r[0]), "=r"(r[1]), "=r"(r[2]), "=r"(r[3]) : "r"(addr));
}
__device__ __forceinline__ void mma_bf16(float d[4], const uint32_t a[4], const uint32_t* b) {
    asm volatile("mma.sync.aligned.m16n8k16.row.col.f32.bf16.bf16.f32 "
                 "{%0,%1,%2,%3}, {%4,%5,%6,%7}, {%8,%9}, {%0,%1,%2,%3};"
                 : "+f"(d[0]), "+f"(d[1]), "+f"(d[2]), "+f"(d[3])
                 : "r"(a[0]), "r"(a[1]), "r"(a[2]), "r"(a[3]), "r"(b[0]), "r"(b[1]));
}
__device__ __forceinline__ void split2(float a, float b, uint32_t& h, uint32_t& l) {
    __nv_bfloat162 hp = __floats2bfloat162_rn(a, b);
    h = *reinterpret_cast<uint32_t*>(&hp);
    float la = a - __bfloat162float(hp.x);
    float lb = b - __bfloat162float(hp.y);
    __nv_bfloat162 lp = __floats2bfloat162_rn(la, lb);
    l = *reinterpret_cast<uint32_t*>(&lp);
}

__inline__ __device__ float warpSum(float v) {
    #pragma unroll
    for (int o = 16; o > 0; o >>= 1) v += __shfl_down_sync(0xffffffffu, v, o);
    return v;
}

// ---- kernel 1: stats + bf16 hi/lo split in ORIGINAL [b][c][hw] layout ----
__global__ __launch_bounds__(256) void stats_kernel(const float* __restrict__ x) {
    const int c = blockIdx.x, b = blockIdx.y;
    const size_t base = ((size_t)b * C_ + c) * HW_;
    const float4* p = (const float4*)(x + base);
    uint2* oh = (uint2*)(g_xh + base);
    uint2* ol = (uint2*)(g_xl + base);
    float s = 0.f, q = 0.f;
    for (int i = threadIdx.x; i < HW_ / 4; i += 256) {
        float4 v = p[i];
        s += v.x + v.y + v.z + v.w;
        q += v.x * v.x + v.y * v.y + v.z * v.z + v.w * v.w;
        uint32_t h0, l0, h1, l1;
        split2(v.x, v.y, h0, l0);
        split2(v.z, v.w, h1, l1);
        oh[i] = make_uint2(h0, h1);
        ol[i] = make_uint2(l0, l1);
    }
    __shared__ float rs[8], rq[8];
    float ws = warpSum(s), wq = warpSum(q);
    int lane = threadIdx.x & 31, warp = threadIdx.x >> 5;
    if (lane == 0) { rs[warp] = ws; rq[warp] = wq; }
    __syncthreads();
    if (threadIdx.x == 0) {
        float ts = 0.f, tq = 0.f;
        #pragma unroll
        for (int w = 0; w < 8; w++) { ts += rs[w]; tq += rq[w]; }
        g_csum[b * C_ + c] = ts;
        g_csumsq[b * C_ + c] = tq;
    }
}

// ---- kernel 2: build A hi/lo (bf16) + folded bias. grid (8 o-chunks, B_) ----
__global__ __launch_bounds__(256) void prep_kernel(const float* __restrict__ params,
                                                   const float* __restrict__ W) {
    const int b = blockIdx.y, o0 = blockIdx.x * 32;
    const int t = threadIdx.x;
    __shared__ float sm_m[C_], sm_r[C_], rs[8], rq[8];
    __shared__ float sM, sR;
    const float cs = g_csum[b * C_ + t];
    const float cq = g_csumsq[b * C_ + t];
    float mean = cs * (1.f / HW_);
    float var  = cq * (1.f / HW_) - mean * mean;
    sm_m[t] = mean;
    sm_r[t] = rsqrtf(var + EPS_);
    float ws = warpSum(cs), wq = warpSum(cq);
    int lane = t & 31, warp = t >> 5;
    if (lane == 0) { rs[warp] = ws; rq[warp] = wq; }
    __syncthreads();
    if (t == 0) {
        float ts = 0.f, tq = 0.f;
        #pragma unroll
        for (int w = 0; w < 8; w++) { ts += rs[w]; tq += rq[w]; }
        float M = ts / (float)CHW_;
        float V = tq / (float)CHW_ - M * M;
        sM = M; sR = rsqrtf(V + EPS_);
    }
    __syncthreads();
    const float M = sM, R = sR;
    const int o = o0 + (t >> 3), lane8 = t & 7, cb = lane8 * 32;
    const float gamma = params[b * 2 * C_ + o];
    const float beta  = params[b * 2 * C_ + C_ + o];
    float accmd = 0.f, accw2 = 0.f;
    uint32_t* ah = (uint32_t*)g_Ah;
    uint32_t* al = (uint32_t*)g_Al;
    #pragma unroll
    for (int j = 0; j < 8; j++) {
        const int c = cb + j * 4;
        float4 w1 = *(const float4*)&W[(size_t)o * 512 + c];
        float4 w2 = *(const float4*)&W[(size_t)o * 512 + 256 + c];
        float r0 = sm_r[c], m0 = sm_m[c], r1 = sm_r[c+1], m1 = sm_m[c+1];
        float r2 = sm_r[c+2], m2 = sm_m[c+2], r3 = sm_r[c+3], m3 = sm_m[c+3];
        accmd += w1.x * r0 * m0 + w1.y * r1 * m1 + w1.z * r2 * m2 + w1.w * r3 * m3;
        accw2 += w2.x + w2.y + w2.z + w2.w;
        float A0 = gamma * (w1.x * r0 + w2.x * R);
        float A1 = gamma * (w1.y * r1 + w2.y * R);
        float A2 = gamma * (w1.z * r2 + w2.z * R);
        float A3 = gamma * (w1.w * r3 + w2.w * R);
        uint32_t h0, l0, h1, l1;
        split2(A0, A1, h0, l0);
        split2(A2, A3, h1, l1);
        const size_t bi = (((size_t)(b * C_ + o)) * C_ + c) >> 1;
        *(uint2*)&ah[bi] = make_uint2(h0, h1);
        *(uint2*)&al[bi] = make_uint2(l0, l1);
    }
    #pragma unroll
    for (int d = 4; d > 0; d >>= 1) {
        accmd += __shfl_down_sync(0xffffffffu, accmd, d, 8);
        accw2 += __shfl_down_sync(0xffffffffu, accw2, d, 8);
    }
    if (lane8 == 0)
        g_dd[b * C_ + o] = gamma * (-accmd - M * R * accw2) + beta;
}

// ---- kernel 3: pure bf16 GEMM pipeline, 1 barrier/chunk, no convert ----------
// CTA: M=128, N=256, Kchunk=32. 8 warps (2m x 4n), warp tile 64x64.
// stage = [A hi/lo: 128x80B x2 = 20480][B hi/lo: 32rows x 528B x2 = 33792]
#define A_STRIDE_ROW 80
#define A_HALF_OFF   10240
#define B_OFF        20480
#define B_HALF       16896
#define STAGE_SZ     54272
#define SMEM_BYTES   162816     // 3 stages

__global__ __launch_bounds__(256, 1) void gemm_kernel(float* __restrict__ out) {
    extern __shared__ char dsm[];
    const uint32_t sb = smem_u32(dsm);
    const int b = blockIdx.z, m0 = blockIdx.y * 128, n0 = blockIdx.x * 256;
    const int t = threadIdx.x, wid = t >> 5, lane = t & 31;
    const int m64w = (wid & 1) * 64, n64w = (wid >> 1) * 64;

    const char* pBh = (const char*)(g_xh + (size_t)b * CHW_ + n0);
    const char* pBl = (const char*)(g_xl + (size_t)b * CHW_ + n0);
    const char* pAh = (const char*)(g_Ah + ((size_t)(b * C_ + m0)) * C_);
    const char* pAl = (const char*)(g_Al + ((size_t)(b * C_ + m0)) * C_);

    auto load_group = [&](int kcc) {
        const uint32_t st = sb + (kcc % 3) * STAGE_SZ;
        #pragma unroll
        for (int i = 0; i < 4; i++) {                 // A: 1024 x 16B (hi 512, lo 512)
            const int idx = t + i * 256;
            const int half = idx >> 9, rr = (idx >> 2) & 127, c4 = idx & 3;
            const char* g = (half ? pAl : pAh) + ((size_t)rr * C_ + kcc * 32) * 2 + c4 * 16;
            cp16(st + half * A_HALF_OFF + rr * A_STRIDE_ROW + c4 * 16, g);
        }
        #pragma unroll
        for (int i = 0; i < 8; i++) {                 // B: 2048 x 16B (hi 1024, lo 1024)
            const int idx = t + i * 256;
            const int half = idx >> 10, cc = idx & 1023;
            const int r = cc >> 5, c32 = cc & 31;     // 32 rows x 512B
            const char* g = (half ? pBl : pBh) + ((size_t)(kcc * 32 + r) * HW_) * 2 + c32 * 16;
            cp16(st + B_OFF + half * B_HALF + r * 528 + c32 * 16, g);
        }
    };

    float acc[4][8][4];
    #pragma unroll
    for (int i = 0; i < 4; i++)
        #pragma unroll
        for (int j = 0; j < 8; j++)
            #pragma unroll
            for (int e = 0; e < 4; e++) acc[i][j][e] = 0.f;

    load_group(0); CP_COMMIT();
    load_group(1); CP_COMMIT();

    for (int kc = 0; kc < 8; kc++) {
        CP_WAIT1();                    // group kc landed (newest may be in flight)
        __syncthreads();               // publish stage kc; frees stage (kc+2)%3 readers

        const uint32_t st = sb + (kc % 3) * STAGE_SZ;
        #pragma unroll
        for (int kk = 0; kk < 2; kk++) {
            uint32_t ahf[4][4], alf[4][4], bhf[4][4], blf[4][4];
            const uint32_t aoff = st + (uint32_t)(m64w + (lane & 15)) * A_STRIDE_ROW
                                + kk * 32 + ((lane >> 4) * 16);
            #pragma unroll
            for (int mt = 0; mt < 4; mt++) {
                ldm4(ahf[mt], aoff + mt * 16 * A_STRIDE_ROW);
                ldm4(alf[mt], aoff + A_HALF_OFF + mt * 16 * A_STRIDE_ROW);
            }
            const int g = lane >> 3;
            const uint32_t krow = (uint32_t)(kk * 16 + ((g & 1) << 3) + (lane & 7));
            const uint32_t boff = st + B_OFF + krow * 528 + (uint32_t)(n64w + ((g >> 1) << 3)) * 2;
            #pragma unroll
            for (int tp = 0; tp < 4; tp++) {
                ldm4t(bhf[tp], boff + tp * 32);
                ldm4t(blf[tp], boff + B_HALF + tp * 32);
            }
            #pragma unroll
            for (int mt = 0; mt < 4; mt++) {
                #pragma unroll
                for (int tp = 0; tp < 4; tp++) {
                    mma_bf16(acc[mt][2 * tp],     ahf[mt], &bhf[tp][0]);
                    mma_bf16(acc[mt][2 * tp + 1], ahf[mt], &bhf[tp][2]);
                    mma_bf16(acc[mt][2 * tp],     ahf[mt], &blf[tp][0]);
                    mma_bf16(acc[mt][2 * tp + 1], ahf[mt], &blf[tp][2]);
                    mma_bf16(acc[mt][2 * tp],     alf[mt], &bhf[tp][0]);
                    mma_bf16(acc[mt][2 * tp + 1], alf[mt], &bhf[tp][2]);
                }
            }
        }

        if (kc + 2 < 8) load_group(kc + 2);
        CP_COMMIT();                   // empty group when done keeps WAIT1 exact
    }

    // ---- epilogue: direct stores; 4-lane groups cover aligned 32B sectors ----
    #pragma unroll
    for (int mt = 0; mt < 4; mt++) {
        const int o = m0 + m64w + mt * 16 + (lane >> 2);
        const float dv0 = g_dd[b * C_ + o];
        const float dv8 = g_dd[b * C_ + o + 8];
        float* r0 = out + ((size_t)(b * C_ + o)) * HW_;
        float* r8 = out + ((size_t)(b * C_ + o + 8)) * HW_;
        #pragma unroll
        for (int n = 0; n < 8; n++) {
            const int hw = n0 + n64w + n * 8 + (lane & 3) * 2;
            float2 v0, v1;
            v0.x = acc[mt][n][0] + dv0; v0.y = acc[mt][n][1] + dv0;
            v1.x = acc[mt][n][2] + dv8; v1.y = acc[mt][n][3] + dv8;
            *(float2*)(r0 + hw) = v0;
            *(float2*)(r8 + hw) = v1;
        }
    }
}

extern "C" void kernel_launch(void* const* d_in, const int* in_sizes, int n_in,
                              void* d_out, int out_size) {
    const float* x      = (const float*)d_in[0];
    const float* params = (const float*)d_in[1];
    const float* W      = (const float*)d_in[2];
    float* out          = (float*)d_out;

    cudaFuncSetAttribute(gemm_kernel, cudaFuncAttributeMaxDynamicSharedMemorySize, SMEM_BYTES);

    stats_kernel<<<dim3(C_, B_), 256>>>(x);
    prep_kernel<<<dim3(8, B_), 256>>>(params, W);
    gemm_kernel<<<dim3(HW_ / 256, C_ / 128, B_), 256, SMEM_BYTES>>>(out);
}